// round 16
// baseline (speedup 1.0000x reference)
#include <cuda_runtime.h>
#include <cuda_bf16.h>

// ---------------- problem constants ----------------
#define Bn   1024
#define Sn   50
#define Hn   128
#define Kn   4
#define Vn   100000
#define KSn  200            // K*S
#define VP   100096         // V padded to 782*128
#define NVT  782            // v tiles of 128
#define NCHUNK 74           // v-tile chunks (74 x 2 m-halves = 148 CTAs)
#define BKH  (Bn*Kn*Hn)     // 524288

typedef unsigned long long ull;

// ---------------- scratch (no allocations allowed) ----------------
__device__ float g_h[Bn*Sn*Hn];        // 26.2 MB  h = seq_emb @ W^T
__device__ float g_cw[KSn*Bn];         // routing logits, [ks][b]
__device__ float g_colsum[KSn];
__device__ float g_tgt[Bn];
__device__ float g_partial[80*Bn];     // exp-sum partials [chunk][b]
__device__ float g_ue_scratch[BKH];
__device__ float g_loss_scratch[4];
// K=32 collapsed operands (score = cap . emb4, exact algebra):
__device__ __align__(256) unsigned g_emb4_u[VP*16];     // 6.4 MB (zero-padded rows)
__device__ __align__(256) unsigned g_best4_u[Bn*16];    // 64 KB (cap row, x log2e)
// bf16 W split for k_h
__device__ __align__(256) unsigned g_wbf_hi[Hn*64];
__device__ __align__(256) unsigned g_wbf_lo[Hn*64];
// grid-barrier state (replay-safe: relative generations, self-resetting counters)
__device__ unsigned g_bar_sub[32];
__device__ unsigned g_bar_root;
__device__ unsigned g_bar_gen;

// ---------------- helpers ----------------
__device__ __forceinline__ float ex2f(float x) {
    float r; asm("ex2.approx.f32 %0, %1;" : "=f"(r) : "f"(x)); return r;
}
__device__ __forceinline__ unsigned smem_u32(const void* p) {
    unsigned a;
    asm("{ .reg .u64 t; cvta.to.shared.u64 t, %1; cvt.u32.u64 %0, t; }" : "=r"(a) : "l"(p));
    return a;
}
__device__ __forceinline__ void cp16(unsigned dst, const void* src) {
    asm volatile("cp.async.cg.shared.global [%0], [%1], 16;" :: "r"(dst), "l"(src) : "memory");
}
#define CP_COMMIT()  asm volatile("cp.async.commit_group;" ::: "memory")
#define CP_WAIT(N)   asm volatile("cp.async.wait_group %0;" :: "n"(N) : "memory")

__device__ __forceinline__ void ldsm_x4(unsigned& r0, unsigned& r1, unsigned& r2, unsigned& r3,
                                        unsigned addr) {
    asm volatile("ldmatrix.sync.aligned.m8n8.x4.shared.b16 {%0,%1,%2,%3}, [%4];"
        : "=r"(r0), "=r"(r1), "=r"(r2), "=r"(r3) : "r"(addr));
}
__device__ __forceinline__ void mma16816(float* c, const unsigned* a, unsigned b0, unsigned b1) {
    asm volatile("mma.sync.aligned.m16n8k16.row.col.f32.bf16.bf16.f32 "
        "{%0,%1,%2,%3}, {%4,%5,%6,%7}, {%8,%9}, {%0,%1,%2,%3};"
        : "+f"(c[0]), "+f"(c[1]), "+f"(c[2]), "+f"(c[3])
        : "r"(a[0]), "r"(a[1]), "r"(a[2]), "r"(a[3]), "r"(b0), "r"(b1));
}
__device__ __forceinline__ unsigned pack_bf16(float x, float y) {
    unsigned lo = (unsigned)__bfloat16_as_ushort(__float2bfloat16(x));
    unsigned hi = (unsigned)__bfloat16_as_ushort(__float2bfloat16(y));
    return lo | (hi << 16);
}
// 64B-row swizzle for K=32 tiles
__device__ __forceinline__ unsigned sw64(int row, int c16) {
    return (unsigned)(row*64 + ((c16 ^ ((row >> 1) & 3)) << 4));
}

// Two-level grid barrier (1024 CTAs). Relative generation: g0 read at entry.
__device__ __forceinline__ void grid_bar(int b, unsigned g0, int target) {
    __syncthreads();
    if (threadIdx.x == 0) {
        __threadfence();
        unsigned o = atomicAdd(&g_bar_sub[b & 31], 1u);
        if (o == 31u) {
            atomicExch(&g_bar_sub[b & 31], 0u);
            unsigned r = atomicAdd(&g_bar_root, 1u);
            if (r == 31u) {
                atomicExch(&g_bar_root, 0u);
                __threadfence();
                atomicAdd(&g_bar_gen, 1u);
            }
        }
        while ((int)(*(volatile unsigned*)&g_bar_gen - g0) < target)
            __nanosleep(64);
        __threadfence();
    }
    __syncthreads();
}

// ---------------- small prep kernels ----------------
// emb fp32 -> emb4 bf16 [v][32]: column c = sum of emb[v][4c..4c+3] (pad rows zero)
__global__ __launch_bounds__(256) void k_conv_emb4(const float* __restrict__ emb) {
    int idx = blockIdx.x * 256 + threadIdx.x;      // VP*16 threads
    int v = idx >> 4, u = idx & 15;
    float c0 = 0.f, c1 = 0.f;
    if (v < Vn) {
        const float4* p = (const float4*)(emb + (ull)v*Hn + u*8);
        float4 a = p[0], b = p[1];
        c0 = a.x + a.y + a.z + a.w;
        c1 = b.x + b.y + b.z + b.w;
    }
    g_emb4_u[idx] = pack_bf16(c0, c1);
}

// W -> bf16 hi/lo split
__global__ __launch_bounds__(256) void k_conv_w(const float* __restrict__ W) {
    int idx = blockIdx.x * 256 + threadIdx.x;
    float2 e = *(const float2*)(W + idx*2);
    __nv_bfloat16 hx = __float2bfloat16(e.x), hy = __float2bfloat16(e.y);
    float lx = e.x - __bfloat162float(hx), ly = e.y - __bfloat162float(hy);
    g_wbf_hi[idx] = ((unsigned)__bfloat16_as_ushort(hx)) | (((unsigned)__bfloat16_as_ushort(hy)) << 16);
    g_wbf_lo[idx] = pack_bf16(lx, ly);
}

// iter-0 colsum straight from cw0 [b][ks]
__global__ __launch_bounds__(256) void k_r1_cw0(const float* __restrict__ cw0) {
    __shared__ float red[256];
    int ks = blockIdx.x, tid = threadIdx.x;
    float sm = 0.f;
    for (int b = tid; b < Bn; b += 256)
        sm += __expf(cw0[(size_t)b*KSn + ks]);
    red[tid] = sm; __syncthreads();
    for (int s = 128; s > 0; s >>= 1) { if (tid < s) red[tid] += red[tid+s]; __syncthreads(); }
    if (tid == 0) g_colsum[ks] = red[0];
}

// ---------------- h = seq_emb @ W^T via split-bf16 HMMA (measured 35us) ----------------
#define KH_SMEM (4*32768)
__global__ __launch_bounds__(256, 1) void k_h_mma(const int* __restrict__ item_seq,
                                                  const float* __restrict__ emb) {
    extern __shared__ char hsm_raw[];
    int tid = threadIdx.x, wid = tid >> 5, lane = tid & 31;
    int blk = blockIdx.x;

    unsigned aH = smem_u32(hsm_raw);
    unsigned aL = aH + 32768u;
    unsigned wH = aH + 65536u;
    unsigned wL = aH + 98304u;

    {
        int row = tid >> 1, c0 = (tid & 1) * 8;
        #pragma unroll
        for (int j = 0; j < 8; j++) {
            int c16 = c0 + j;
            cp16(wH + row*256 + ((c16 ^ (row & 7)) << 4), (const char*)g_wbf_hi + row*256 + c16*16);
            cp16(wL + row*256 + ((c16 ^ (row & 7)) << 4), (const char*)g_wbf_lo + row*256 + c16*16);
        }
    }
    CP_COMMIT();

    {
        int row = tid >> 1, half = tid & 1;
        int idx = item_seq[blk*128 + row];
        const float* src = emb + (size_t)idx*Hn + half*64;
        bool z = (idx == 0);
        #pragma unroll
        for (int j = 0; j < 8; j++) {
            int c16 = half*8 + j;
            float4 f0 = z ? make_float4(0,0,0,0) : *(const float4*)(src + j*8);
            float4 f1 = z ? make_float4(0,0,0,0) : *(const float4*)(src + j*8 + 4);
            uint4 hiq, loq;
            {
                __nv_bfloat16 h0=__float2bfloat16(f0.x), h1=__float2bfloat16(f0.y);
                __nv_bfloat16 h2=__float2bfloat16(f0.z), h3=__float2bfloat16(f0.w);
                __nv_bfloat16 h4=__float2bfloat16(f1.x), h5=__float2bfloat16(f1.y);
                __nv_bfloat16 h6=__float2bfloat16(f1.z), h7=__float2bfloat16(f1.w);
                hiq.x = ((unsigned)__bfloat16_as_ushort(h0)) | (((unsigned)__bfloat16_as_ushort(h1))<<16);
                hiq.y = ((unsigned)__bfloat16_as_ushort(h2)) | (((unsigned)__bfloat16_as_ushort(h3))<<16);
                hiq.z = ((unsigned)__bfloat16_as_ushort(h4)) | (((unsigned)__bfloat16_as_ushort(h5))<<16);
                hiq.w = ((unsigned)__bfloat16_as_ushort(h6)) | (((unsigned)__bfloat16_as_ushort(h7))<<16);
                loq.x = pack_bf16(f0.x-__bfloat162float(h0), f0.y-__bfloat162float(h1));
                loq.y = pack_bf16(f0.z-__bfloat162float(h2), f0.w-__bfloat162float(h3));
                loq.z = pack_bf16(f1.x-__bfloat162float(h4), f1.y-__bfloat162float(h5));
                loq.w = pack_bf16(f1.z-__bfloat162float(h6), f1.w-__bfloat162float(h7));
            }
            unsigned off = row*256 + ((c16 ^ (row & 7)) << 4);
            asm volatile("st.shared.v4.b32 [%0], {%1,%2,%3,%4};" :: "r"(aH+off),
                         "r"(hiq.x), "r"(hiq.y), "r"(hiq.z), "r"(hiq.w) : "memory");
            asm volatile("st.shared.v4.b32 [%0], {%1,%2,%3,%4};" :: "r"(aL+off),
                         "r"(loq.x), "r"(loq.y), "r"(loq.z), "r"(loq.w) : "memory");
        }
    }
    CP_WAIT(0);
    __syncthreads();

    int rA = wid*16 + (lane & 7) + ((lane >> 3) & 1) * 8;
    int kcA = lane >> 4;
    unsigned ah[8][4], al[8][4];
    #pragma unroll
    for (int k = 0; k < 8; k++) {
        int c16 = k*2 + kcA;
        unsigned off = rA*256 + ((c16 ^ (rA & 7)) << 4);
        ldsm_x4(ah[k][0], ah[k][1], ah[k][2], ah[k][3], aH + off);
        ldsm_x4(al[k][0], al[k][1], al[k][2], al[k][3], aL + off);
    }

    int rBl = ((lane >> 4) & 1) * 8 + (lane & 7);
    int khB = (lane >> 3) & 1;
    #pragma unroll 1
    for (int np = 0; np < 8; np++) {
        int rB = np*16 + rBl;
        float cc[8];
        #pragma unroll
        for (int j = 0; j < 8; j++) cc[j] = 0.f;
        #pragma unroll
        for (int k = 0; k < 8; k++) {
            int c16 = k*2 + khB;
            unsigned off = rB*256 + ((c16 ^ (rB & 7)) << 4);
            unsigned bh0, bh1, bh2, bh3, bl0, bl1, bl2, bl3;
            ldsm_x4(bh0, bh1, bh2, bh3, wH + off);
            ldsm_x4(bl0, bl1, bl2, bl3, wL + off);
            mma16816(cc,     ah[k], bh0, bh1);
            mma16816(cc + 4, ah[k], bh2, bh3);
            mma16816(cc,     ah[k], bl0, bl1);
            mma16816(cc + 4, ah[k], bl2, bl3);
            mma16816(cc,     al[k], bh0, bh1);
            mma16816(cc + 4, al[k], bh2, bh3);
        }
        int mrow = blk*128 + wid*16 + (lane >> 2);
        int col  = np*16 + (lane & 3)*2;
        *(float2*)&g_h[(size_t)mrow*Hn + col]         = make_float2(cc[0], cc[1]);
        *(float2*)&g_h[(size_t)(mrow+8)*Hn + col]     = make_float2(cc[2], cc[3]);
        *(float2*)&g_h[(size_t)mrow*Hn + col + 8]     = make_float2(cc[4], cc[5]);
        *(float2*)&g_h[(size_t)(mrow+8)*Hn + col + 8] = make_float2(cc[6], cc[7]);
    }
}

// ---------------- persistent routing: all 3 iterations, h loaded ONCE ----------------
// 1024 CTAs (one per b), 128 threads, all co-resident (7/SM, ~28.5KB smem each).
__global__ __launch_bounds__(128, 7) void k_route(const float* __restrict__ mask,
                                                  const float* __restrict__ cw0,
                                                  const int* __restrict__ item,
                                                  const float* __restrict__ emb,
                                                  float* __restrict__ ue_out) {
    __shared__ float hsm[Sn*Hn];        // 25.6 KB
    __shared__ float swsm[KSn];
    __shared__ float cwsm[KSn];
    __shared__ float capsm[128];
    __shared__ float msm[Sn];
    __shared__ float ie4sm[32], ie4rsm[32];
    __shared__ float cossm[4], cosrm[4];
    __shared__ float redsm[128];
    __shared__ int ksel;
    int b = blockIdx.x, tid = threadIdx.x;

    unsigned g0 = 0;
    if (tid == 0) g0 = *(volatile unsigned*)&g_bar_gen;   // pre-arrival: race-free

    // one-time loads
    {
        const float4* hp = (const float4*)(g_h + (size_t)b*Sn*Hn);
        for (int i = tid; i < Sn*Hn/4; i += 128) ((float4*)hsm)[i] = hp[i];
        if (tid < Sn) msm[tid] = mask[b*Sn + tid];
        if (tid < 32) {
            int idx = item[b];
            float4 v = ((const float4*)emb)[idx*32 + tid];
            float s = v.x + v.y + v.z + v.w;
            ie4rsm[tid] = s;
            ie4sm[tid]  = (idx != 0) ? s : 0.f;
        }
    }

    int k = tid >> 5, c = tid & 31;
    int bar = 0;

    #pragma unroll 1
    for (int it = 0; it < 3; it++) {
        // ---- logits + softmax weights ----
        // iter 0: cw0 coalesced per-b; iter>=1: g_cw transposed (colsum just computed)
        for (int t = tid; t < KSn; t += 128) {
            int s = t % Sn;
            float cwv = (it == 0) ? cw0[(size_t)b*KSn + t] : g_cw[(size_t)t*Bn + b];
            cwsm[t] = cwv;
            swsm[t] = (msm[s] != 0.f) ? __expf(cwv) / g_colsum[t] : 0.f;
        }
        __syncthreads();

        float g = 0.f;
        #pragma unroll
        for (int s = 0; s < Sn; s++) g += swsm[k*Sn + s] * hsm[s*Hn + k*32 + c];
        float n = g*g;
        #pragma unroll
        for (int o = 16; o; o >>= 1) n += __shfl_xor_sync(0xffffffffu, n, o);
        n *= 4.f;
        float sc = n / (1.f + n) / sqrtf(n + 1e-9f);
        float cap = sc * g;
        capsm[tid] = cap;

        if (it == 2) {
            float cz = cap * ie4sm[c];
            float cr = cap * ie4rsm[c];
            #pragma unroll
            for (int o = 16; o; o >>= 1) {
                cz += __shfl_xor_sync(0xffffffffu, cz, o);
                cr += __shfl_xor_sync(0xffffffffu, cr, o);
            }
            if (c == 0) { cossm[k] = cz; cosrm[k] = cr; }
        }
        __syncthreads();

        if (it < 2) {
            // delta[k,s] = 4 * sum_c cap[k,c]*h[s,k*32+c]; pure store (cwsm holds base)
            #pragma unroll
            for (int pass = 0; pass < 2; pass++) {
                int s = c + pass*32;
                if (s < Sn) {
                    float d = 0.f;
                    #pragma unroll
                    for (int i = 0; i < 32; i++) {
                        int cc2 = (c + i) & 31;
                        d += capsm[k*32 + cc2] * hsm[s*Hn + k*32 + cc2];
                    }
                    g_cw[(size_t)(k*Sn + s)*Bn + b] = cwsm[k*Sn + s] + 4.f * d;
                }
            }
            grid_bar(b, g0, ++bar);     // all logits written

            // colsum for next iteration (CTAs 0..199, coalesced over b)
            if (b < KSn) {
                const float* col = g_cw + (size_t)b*Bn;
                float s = 0.f;
                #pragma unroll
                for (int j = 0; j < 8; j++) s += __expf(col[tid + j*128]);
                redsm[tid] = s; __syncthreads();
                for (int o = 64; o; o >>= 1) { if (tid < o) redsm[tid] += redsm[tid+o]; __syncthreads(); }
                if (tid == 0) g_colsum[b] = redsm[0];
            }
            grid_bar(b, g0, ++bar);     // colsums visible
        }
    }

    // ---- final outputs ----
    if (tid == 0) {
        float bst = -3.4e38f; int kb = 0;
        #pragma unroll
        for (int kk = 0; kk < 4; kk++) if (cossm[kk] > bst) { bst = cossm[kk]; kb = kk; }
        ksel = kb;
        g_tgt[b] = cosrm[kb];
    }
    __syncthreads();
    for (int t = tid; t < 512; t += 128) {
        int kk = t >> 7, j = t & 127;
        ue_out[b*512 + t] = capsm[kk*32 + (j >> 2)];
    }
    if (tid < 16) {
        const float L2E = 1.4426950408889634f;
        float x = capsm[ksel*32 + 2*tid]     * L2E;
        float y = capsm[ksel*32 + 2*tid + 1] * L2E;
        g_best4_u[b*16 + tid] = pack_bf16(x, y);
    }
}

// ---------------- scores GEMM, K=32 + fused exp2 row-sum ----------------
#define KD_SMEM (49152)
__device__ __forceinline__ void load_tileB(unsigned sbase, const char* gsrc, int tid) {
    int row = tid >> 1;
    int c0  = (tid & 1) * 2;
    #pragma unroll
    for (int j = 0; j < 2; j++) {
        int c16 = c0 + j;
        cp16(sbase + sw64(row, c16), gsrc + row*64 + c16*16);
    }
}

__global__ __launch_bounds__(256, 1) void k_d_mma() {
    extern __shared__ char dsm[];
    int tid = threadIdx.x, wid = tid >> 5, lane = tid & 31;
    int mhalf = blockIdx.y, c = blockIdx.x;
    int t0  = c*10 + min(c, 42);          // 42 chunks of 11 tiles, 32 of 10
    int cnt = 10 + (c < 42 ? 1 : 0);

    unsigned aS = smem_u32(dsm);          // A: 512 rows x 64B = 32KB
    unsigned bS[2] = { aS + 32768u, aS + 40960u };

    {
        const char* aG = (const char*)g_best4_u + (size_t)mhalf * 32768;
        #pragma unroll
        for (int rr = 0; rr < 2; rr++) {
            int row = tid + rr*256;
            #pragma unroll
            for (int j = 0; j < 4; j++)
                cp16(aS + sw64(row, j), aG + row*64 + j*16);
        }
    }
    load_tileB(bS[0], (const char*)g_emb4_u + (size_t)t0 * 8192, tid);
    CP_COMMIT();

    int rloc = (lane & 7) + ((lane >> 3) & 1) * 8;
    int kcA = lane >> 4;
    int rBl = ((lane >> 4) & 1) * 8 + (lane & 7);
    int khB = (lane >> 3) & 1;

    unsigned a[4][2][4];
    float acc[8];
    #pragma unroll
    for (int j = 0; j < 8; j++) acc[j] = 0.f;

    #pragma unroll 1
    for (int t = 0; t < cnt; t++) {
        if (t + 1 < cnt) {
            load_tileB(bS[(t + 1) & 1], (const char*)g_emb4_u + (size_t)(t0 + t + 1) * 8192, tid);
            CP_COMMIT();
            CP_WAIT(1);
        } else {
            CP_WAIT(0);
        }
        __syncthreads();

        if (t == 0) {
            #pragma unroll
            for (int f = 0; f < 4; f++) {
                int r = wid*64 + f*16 + rloc;
                #pragma unroll
                for (int k = 0; k < 2; k++) {
                    int c16 = k*2 + kcA;
                    ldsm_x4(a[f][k][0], a[f][k][1], a[f][k][2], a[f][k][3],
                            aS + sw64(r, c16));
                }
            }
        }

        unsigned bb = bS[t & 1];
        #pragma unroll 1
        for (int np = 0; np < 8; np++) {
            int rB = np*16 + rBl;
            float cc[32];
            #pragma unroll
            for (int j = 0; j < 32; j++) cc[j] = 0.f;
            #pragma unroll
            for (int k = 0; k < 2; k++) {
                int c16 = k*2 + khB;
                unsigned b0, b1, b2, b3;
                ldsm_x4(b0, b1, b2, b3, bb + sw64(rB, c16));
                #pragma unroll
                for (int f = 0; f < 4; f++) {
                    mma16816(cc + f*8,     a[f][k], b0, b1);
                    mma16816(cc + f*8 + 4, a[f][k], b2, b3);
                }
            }
            #pragma unroll
            for (int f = 0; f < 4; f++) {
                acc[f*2]   += ex2f(cc[f*8+0]) + ex2f(cc[f*8+1]) + ex2f(cc[f*8+4]) + ex2f(cc[f*8+5]);
                acc[f*2+1] += ex2f(cc[f*8+2]) + ex2f(cc[f*8+3]) + ex2f(cc[f*8+6]) + ex2f(cc[f*8+7]);
            }
        }
        __syncthreads();
    }

    #pragma unroll
    for (int j = 0; j < 8; j++) {
        acc[j] += __shfl_xor_sync(0xffffffffu, acc[j], 1);
        acc[j] += __shfl_xor_sync(0xffffffffu, acc[j], 2);
    }
    if ((lane & 3) == 0) {
        int r0 = mhalf*512 + wid*64 + (lane >> 2);
        #pragma unroll
        for (int f = 0; f < 4; f++) {
            g_partial[c*Bn + r0 + f*16]     = acc[f*2];
            g_partial[c*Bn + r0 + f*16 + 8] = acc[f*2+1];
        }
    }
}

// ---------------- final loss reduction ----------------
__global__ __launch_bounds__(1024) void k_e(float* __restrict__ loss_out) {
    __shared__ float red[1024];
    int tid = threadIdx.x;
    float acc = -96.0f;   // remove exp(0)=1 from the 96 zero-padded v columns
    for (int c = 0; c < NCHUNK; c++) acc += g_partial[c*Bn + tid];
    red[tid] = g_tgt[tid] - logf(acc);
    __syncthreads();
    for (int s = 512; s > 0; s >>= 1) { if (tid < s) red[tid] += red[tid+s]; __syncthreads(); }
    if (tid == 0) loss_out[0] = -red[0] / (float)Bn;
}

// ---------------- host launcher ----------------
extern "C" void kernel_launch(void* const* d_in, const int* in_sizes, int n_in,
                              void* d_out, int out_size) {
    const int*   item_seq = (const int*)  d_in[0];
    const float* mask     = (const float*)d_in[1];
    const int*   item     = (const int*)  d_in[2];
    const float* emb      = (const float*)d_in[3];
    const float* W        = (const float*)d_in[4];
    const float* cw0      = (const float*)d_in[5];
    float* out = (float*)d_out;

    float *ue_ptr, *loss_ptr;
    if (out_size >= BKH + 1)      { ue_ptr = out;          loss_ptr = out + BKH; }
    else if (out_size == BKH)     { ue_ptr = out;          loss_ptr = g_loss_scratch; }
    else                          { ue_ptr = g_ue_scratch; loss_ptr = out + (out_size > 0 ? out_size - 1 : 0); }

    cudaFuncSetAttribute(k_h_mma, cudaFuncAttributeMaxDynamicSharedMemorySize, KH_SMEM);
    cudaFuncSetAttribute(k_d_mma, cudaFuncAttributeMaxDynamicSharedMemorySize, KD_SMEM);

    cudaStream_t s2; cudaEvent_t evF, evR, evE;
    cudaStreamCreateWithFlags(&s2, cudaStreamNonBlocking);
    cudaEventCreateWithFlags(&evF, cudaEventDisableTiming);
    cudaEventCreateWithFlags(&evR, cudaEventDisableTiming);
    cudaEventCreateWithFlags(&evE, cudaEventDisableTiming);
    cudaEventRecord(evF, 0);
    cudaStreamWaitEvent(s2, evF, 0);

    // launch #1 (s2): iter-0 colsum straight from cw0
    k_r1_cw0<<<KSn, 256, 0, s2>>>(cw0);
    cudaEventRecord(evR, s2);

    // launches #2, #3 (main): conv_w -> k_h
    k_conv_w<<<(Hn*64)/256, 256>>>(W);
    k_h_mma<<<(Bn*Sn)/128, 256, KH_SMEM>>>(item_seq, emb);

    cudaStreamWaitEvent(0, evR, 0);
    // launch #4 (main): persistent routing  <-- ncu capture slot
    k_route<<<Bn, 128>>>(mask, cw0, item, emb, ue_ptr);

    // launch #5 (s2): emb4 conversion (concurrent with k_h; zero smem, co-residency
    // safe with k_route even in the worst-case overlap)
    k_conv_emb4<<<(VP*16)/256, 256, 0, s2>>>(emb);
    cudaEventRecord(evE, s2);

    cudaStreamWaitEvent(0, evE, 0);              // emb4 ready
    k_d_mma<<<dim3(NCHUNK, 2), 256, KD_SMEM>>>();
    k_e<<<1, 1024>>>(loss_ptr);
}

// round 17
// speedup vs baseline: 1.0082x; 1.0082x over previous
#include <cuda_runtime.h>
#include <cuda_bf16.h>

// ---------------- problem constants ----------------
#define Bn   1024
#define Sn   50
#define Hn   128
#define Kn   4
#define Vn   100000
#define KSn  200            // K*S
#define VP   100096         // V padded to 782*128
#define NVT  782            // v tiles of 128
#define NCHUNK 74           // v-tile chunks (74 x 2 m-halves = 148 CTAs)
#define BKH  (Bn*Kn*Hn)     // 524288

typedef unsigned long long ull;

// ---------------- scratch (no allocations allowed) ----------------
__device__ float g_h[Bn*Sn*Hn];        // 26.2 MB  h = seq_emb @ W^T
__device__ float g_cw[KSn*Bn];         // routing logits, [ks][b]
__device__ float g_colsum[KSn];
__device__ float g_tgt[Bn];
__device__ float g_partial[80*Bn];     // exp-sum partials [chunk][b]
__device__ float g_ue_scratch[BKH];
__device__ float g_loss_scratch[4];
// K=32 collapsed operands (score = cap . emb4, exact algebra):
__device__ __align__(256) unsigned g_emb4_u[VP*16];     // 6.4 MB (zero-padded rows)
__device__ __align__(256) unsigned g_best4_u[Bn*16];    // 64 KB (cap row, x log2e)
// bf16 W split for k_h
__device__ __align__(256) unsigned g_wbf_hi[Hn*64];
__device__ __align__(256) unsigned g_wbf_lo[Hn*64];

// ---------------- helpers ----------------
__device__ __forceinline__ float ex2f(float x) {
    float r; asm("ex2.approx.f32 %0, %1;" : "=f"(r) : "f"(x)); return r;
}
__device__ __forceinline__ unsigned smem_u32(const void* p) {
    unsigned a;
    asm("{ .reg .u64 t; cvta.to.shared.u64 t, %1; cvt.u32.u64 %0, t; }" : "=r"(a) : "l"(p));
    return a;
}
__device__ __forceinline__ void cp16(unsigned dst, const void* src) {
    asm volatile("cp.async.cg.shared.global [%0], [%1], 16;" :: "r"(dst), "l"(src) : "memory");
}
#define CP_COMMIT()  asm volatile("cp.async.commit_group;" ::: "memory")
#define CP_WAIT(N)   asm volatile("cp.async.wait_group %0;" :: "n"(N) : "memory")

__device__ __forceinline__ void ldsm_x4(unsigned& r0, unsigned& r1, unsigned& r2, unsigned& r3,
                                        unsigned addr) {
    asm volatile("ldmatrix.sync.aligned.m8n8.x4.shared.b16 {%0,%1,%2,%3}, [%4];"
        : "=r"(r0), "=r"(r1), "=r"(r2), "=r"(r3) : "r"(addr));
}
__device__ __forceinline__ void mma16816(float* c, const unsigned* a, unsigned b0, unsigned b1) {
    asm volatile("mma.sync.aligned.m16n8k16.row.col.f32.bf16.bf16.f32 "
        "{%0,%1,%2,%3}, {%4,%5,%6,%7}, {%8,%9}, {%0,%1,%2,%3};"
        : "+f"(c[0]), "+f"(c[1]), "+f"(c[2]), "+f"(c[3])
        : "r"(a[0]), "r"(a[1]), "r"(a[2]), "r"(a[3]), "r"(b0), "r"(b1));
}
__device__ __forceinline__ unsigned pack_bf16(float x, float y) {
    unsigned lo = (unsigned)__bfloat16_as_ushort(__float2bfloat16(x));
    unsigned hi = (unsigned)__bfloat16_as_ushort(__float2bfloat16(y));
    return lo | (hi << 16);
}
// 64B-row swizzle for K=32 tiles
__device__ __forceinline__ unsigned sw64(int row, int c16) {
    return (unsigned)(row*64 + ((c16 ^ ((row >> 1) & 3)) << 4));
}

// ---------------- small prep kernels ----------------
// emb fp32 -> emb4 bf16 [v][32]: column c = sum of emb[v][4c..4c+3] (pad rows zero)
__global__ __launch_bounds__(256) void k_conv_emb4(const float* __restrict__ emb) {
    int idx = blockIdx.x * 256 + threadIdx.x;      // VP*16 threads
    int v = idx >> 4, u = idx & 15;
    float c0 = 0.f, c1 = 0.f;
    if (v < Vn) {
        const float4* p = (const float4*)(emb + (ull)v*Hn + u*8);
        float4 a = p[0], b = p[1];
        c0 = a.x + a.y + a.z + a.w;
        c1 = b.x + b.y + b.z + b.w;
    }
    g_emb4_u[idx] = pack_bf16(c0, c1);
}

// W -> bf16 hi/lo split
__global__ __launch_bounds__(256) void k_conv_w(const float* __restrict__ W) {
    int idx = blockIdx.x * 256 + threadIdx.x;
    float2 e = *(const float2*)(W + idx*2);
    __nv_bfloat16 hx = __float2bfloat16(e.x), hy = __float2bfloat16(e.y);
    float lx = e.x - __bfloat162float(hx), ly = e.y - __bfloat162float(hy);
    g_wbf_hi[idx] = ((unsigned)__bfloat16_as_ushort(hx)) | (((unsigned)__bfloat16_as_ushort(hy)) << 16);
    g_wbf_lo[idx] = pack_bf16(lx, ly);
}

// ---------------- h = seq_emb @ W^T via split-bf16 HMMA (measured 35us) ----------------
#define KH_SMEM (4*32768)
__global__ __launch_bounds__(256, 1) void k_h_mma(const int* __restrict__ item_seq,
                                                  const float* __restrict__ emb) {
    extern __shared__ char hsm_raw[];
    int tid = threadIdx.x, wid = tid >> 5, lane = tid & 31;
    int blk = blockIdx.x;

    unsigned aH = smem_u32(hsm_raw);
    unsigned aL = aH + 32768u;
    unsigned wH = aH + 65536u;
    unsigned wL = aH + 98304u;

    {
        int row = tid >> 1, c0 = (tid & 1) * 8;
        #pragma unroll
        for (int j = 0; j < 8; j++) {
            int c16 = c0 + j;
            cp16(wH + row*256 + ((c16 ^ (row & 7)) << 4), (const char*)g_wbf_hi + row*256 + c16*16);
            cp16(wL + row*256 + ((c16 ^ (row & 7)) << 4), (const char*)g_wbf_lo + row*256 + c16*16);
        }
    }
    CP_COMMIT();

    {
        int row = tid >> 1, half = tid & 1;
        int idx = item_seq[blk*128 + row];
        const float* src = emb + (size_t)idx*Hn + half*64;
        bool z = (idx == 0);
        #pragma unroll
        for (int j = 0; j < 8; j++) {
            int c16 = half*8 + j;
            float4 f0 = z ? make_float4(0,0,0,0) : *(const float4*)(src + j*8);
            float4 f1 = z ? make_float4(0,0,0,0) : *(const float4*)(src + j*8 + 4);
            uint4 hiq, loq;
            {
                __nv_bfloat16 h0=__float2bfloat16(f0.x), h1=__float2bfloat16(f0.y);
                __nv_bfloat16 h2=__float2bfloat16(f0.z), h3=__float2bfloat16(f0.w);
                __nv_bfloat16 h4=__float2bfloat16(f1.x), h5=__float2bfloat16(f1.y);
                __nv_bfloat16 h6=__float2bfloat16(f1.z), h7=__float2bfloat16(f1.w);
                hiq.x = ((unsigned)__bfloat16_as_ushort(h0)) | (((unsigned)__bfloat16_as_ushort(h1))<<16);
                hiq.y = ((unsigned)__bfloat16_as_ushort(h2)) | (((unsigned)__bfloat16_as_ushort(h3))<<16);
                hiq.z = ((unsigned)__bfloat16_as_ushort(h4)) | (((unsigned)__bfloat16_as_ushort(h5))<<16);
                hiq.w = ((unsigned)__bfloat16_as_ushort(h6)) | (((unsigned)__bfloat16_as_ushort(h7))<<16);
                loq.x = pack_bf16(f0.x-__bfloat162float(h0), f0.y-__bfloat162float(h1));
                loq.y = pack_bf16(f0.z-__bfloat162float(h2), f0.w-__bfloat162float(h3));
                loq.z = pack_bf16(f1.x-__bfloat162float(h4), f1.y-__bfloat162float(h5));
                loq.w = pack_bf16(f1.z-__bfloat162float(h6), f1.w-__bfloat162float(h7));
            }
            unsigned off = row*256 + ((c16 ^ (row & 7)) << 4);
            asm volatile("st.shared.v4.b32 [%0], {%1,%2,%3,%4};" :: "r"(aH+off),
                         "r"(hiq.x), "r"(hiq.y), "r"(hiq.z), "r"(hiq.w) : "memory");
            asm volatile("st.shared.v4.b32 [%0], {%1,%2,%3,%4};" :: "r"(aL+off),
                         "r"(loq.x), "r"(loq.y), "r"(loq.z), "r"(loq.w) : "memory");
        }
    }
    CP_WAIT(0);
    __syncthreads();

    int rA = wid*16 + (lane & 7) + ((lane >> 3) & 1) * 8;
    int kcA = lane >> 4;
    unsigned ah[8][4], al[8][4];
    #pragma unroll
    for (int k = 0; k < 8; k++) {
        int c16 = k*2 + kcA;
        unsigned off = rA*256 + ((c16 ^ (rA & 7)) << 4);
        ldsm_x4(ah[k][0], ah[k][1], ah[k][2], ah[k][3], aH + off);
        ldsm_x4(al[k][0], al[k][1], al[k][2], al[k][3], aL + off);
    }

    int rBl = ((lane >> 4) & 1) * 8 + (lane & 7);
    int khB = (lane >> 3) & 1;
    #pragma unroll 1
    for (int np = 0; np < 8; np++) {
        int rB = np*16 + rBl;
        float cc[8];
        #pragma unroll
        for (int j = 0; j < 8; j++) cc[j] = 0.f;
        #pragma unroll
        for (int k = 0; k < 8; k++) {
            int c16 = k*2 + khB;
            unsigned off = rB*256 + ((c16 ^ (rB & 7)) << 4);
            unsigned bh0, bh1, bh2, bh3, bl0, bl1, bl2, bl3;
            ldsm_x4(bh0, bh1, bh2, bh3, wH + off);
            ldsm_x4(bl0, bl1, bl2, bl3, wL + off);
            mma16816(cc,     ah[k], bh0, bh1);
            mma16816(cc + 4, ah[k], bh2, bh3);
            mma16816(cc,     ah[k], bl0, bl1);
            mma16816(cc + 4, ah[k], bl2, bl3);
            mma16816(cc,     al[k], bh0, bh1);
            mma16816(cc + 4, al[k], bh2, bh3);
        }
        int mrow = blk*128 + wid*16 + (lane >> 2);
        int col  = np*16 + (lane & 3)*2;
        *(float2*)&g_h[(size_t)mrow*Hn + col]         = make_float2(cc[0], cc[1]);
        *(float2*)&g_h[(size_t)(mrow+8)*Hn + col]     = make_float2(cc[2], cc[3]);
        *(float2*)&g_h[(size_t)mrow*Hn + col + 8]     = make_float2(cc[4], cc[5]);
        *(float2*)&g_h[(size_t)(mrow+8)*Hn + col + 8] = make_float2(cc[6], cc[7]);
    }
}

// ---------------- routing: column exp-sum (softmax over batch axis) ----------------
template<bool FROM_CW0>
__global__ __launch_bounds__(256) void k_r1(const float* __restrict__ cw0) {
    __shared__ float red[256];
    int ks = blockIdx.x, tid = threadIdx.x;
    float sm = 0.f;
    for (int b = tid; b < Bn; b += 256)
        sm += __expf(FROM_CW0 ? cw0[(size_t)b*KSn + ks] : g_cw[(size_t)ks*Bn + b]);
    red[tid] = sm; __syncthreads();
    for (int s = 128; s > 0; s >>= 1) { if (tid < s) red[tid] += red[tid+s]; __syncthreads(); }
    if (tid == 0) g_colsum[ks] = red[0];
}

// ---------------- routing: per-batch capsule update (256 threads) ----------------
// PHASE 0: first iter (read cw0, write g_cw). PHASE 1: middle. PHASE 2: final.
template<int PHASE>
__global__ __launch_bounds__(256) void k_r2(const float* __restrict__ mask,
                                            const float* __restrict__ cw0,
                                            const int* __restrict__ item,
                                            const float* __restrict__ emb,
                                            float* __restrict__ ue_out) {
    __shared__ float hsm[Sn*Hn];        // 25.6 KB
    __shared__ float swsm[KSn];
    __shared__ float cwsm[KSn];
    __shared__ float psum[256];
    __shared__ float capsm[128];
    __shared__ float ie4sm[32], ie4rsm[32];
    __shared__ float cossm[4], cosrm[4];
    __shared__ int ksel;
    int b = blockIdx.x, tid = threadIdx.x;

    // h load: 256 threads x 6.25 float4 (vs 12.5 at 128 threads)
    const float4* hp = (const float4*)(g_h + (size_t)b*Sn*Hn);
    for (int i = tid; i < Sn*Hn/4; i += 256) ((float4*)hsm)[i] = hp[i];
    if (tid < KSn) {
        int s = tid % Sn;
        float cwv = (PHASE == 0) ? cw0[(size_t)b*KSn + tid] : g_cw[(size_t)tid*Bn + b];
        cwsm[tid] = cwv;
        float m = mask[b*Sn + s];
        swsm[tid] = (m != 0.f) ? __expf(cwv) / g_colsum[tid] : 0.f;
    }
    if (PHASE == 2 && tid >= 224) {     // warp 7 loads the item-embedding group sums
        int cix = tid - 224;
        int idx = item[b];
        float4 v = ((const float4*)emb)[idx*32 + cix];
        float s = v.x + v.y + v.z + v.w;
        ie4rsm[cix] = s;
        ie4sm[cix]  = (idx != 0) ? s : 0.f;
    }
    __syncthreads();

    // split-s partial dot: k=tid>>6, half=bit5, c=lane
    {
        int k = tid >> 6, half = (tid >> 5) & 1, c = tid & 31;
        int s0 = half * 25;
        float gp = 0.f;
        #pragma unroll
        for (int s = 0; s < 25; s++)
            gp += swsm[k*Sn + s0 + s] * hsm[(s0 + s)*Hn + k*32 + c];
        psum[tid] = gp;
    }
    __syncthreads();

    // combine + squash on 128 threads
    if (tid < 128) {
        int k = tid >> 5, c = tid & 31;
        float g = psum[k*64 + c] + psum[k*64 + 32 + c];
        float n = g*g;
        #pragma unroll
        for (int o = 16; o; o >>= 1) n += __shfl_xor_sync(0xffffffffu, n, o);
        n *= 4.f;
        float sc = n / (1.f + n) / sqrtf(n + 1e-9f);
        float cap = sc * g;
        capsm[tid] = cap;
        if (PHASE == 2) {
            float cz = cap * ie4sm[c];
            float cr = cap * ie4rsm[c];
            #pragma unroll
            for (int o = 16; o; o >>= 1) {
                cz += __shfl_xor_sync(0xffffffffu, cz, o);
                cr += __shfl_xor_sync(0xffffffffu, cr, o);
            }
            if (c == 0) { cossm[k] = cz; cosrm[k] = cr; }
        }
    }
    __syncthreads();

    if (PHASE < 2) {
        // one (k,s) pair per thread (200 active); rotated-c indexing, conflict-free
        if (tid < KSn) {
            int k = tid / Sn, s = tid % Sn;
            float d = 0.f;
            #pragma unroll
            for (int i = 0; i < 32; i++) {
                int c2 = (tid + i) & 31;
                d += capsm[k*32 + c2] * hsm[s*Hn + k*32 + c2];
            }
            g_cw[(size_t)tid*Bn + b] = cwsm[tid] + 4.f * d;
        }
    } else {
        if (tid == 0) {
            float bst = -3.4e38f; int kb = 0;
            #pragma unroll
            for (int kk = 0; kk < 4; kk++) if (cossm[kk] > bst) { bst = cossm[kk]; kb = kk; }
            ksel = kb;
            g_tgt[b] = cosrm[kb];         // target score uses RAW emb row
        }
        __syncthreads();
        #pragma unroll
        for (int t = tid; t < 512; t += 256) {
            int kk = t >> 7, j = t & 127;
            ue_out[b*512 + t] = capsm[kk*32 + (j >> 2)];
        }
        if (tid < 16) {
            const float L2E = 1.4426950408889634f;
            float x = capsm[ksel*32 + 2*tid]     * L2E;
            float y = capsm[ksel*32 + 2*tid + 1] * L2E;
            g_best4_u[b*16 + tid] = pack_bf16(x, y);
        }
    }
}

// ---------------- scores GEMM, K=32 + fused exp2 row-sum ----------------
#define KD_SMEM (49152)
__device__ __forceinline__ void load_tileB(unsigned sbase, const char* gsrc, int tid) {
    int row = tid >> 1;
    int c0  = (tid & 1) * 2;
    #pragma unroll
    for (int j = 0; j < 2; j++) {
        int c16 = c0 + j;
        cp16(sbase + sw64(row, c16), gsrc + row*64 + c16*16);
    }
}

__global__ __launch_bounds__(256, 1) void k_d_mma() {
    extern __shared__ char dsm[];
    int tid = threadIdx.x, wid = tid >> 5, lane = tid & 31;
    int mhalf = blockIdx.y, c = blockIdx.x;
    int t0  = c*10 + min(c, 42);          // 42 chunks of 11 tiles, 32 of 10
    int cnt = 10 + (c < 42 ? 1 : 0);

    unsigned aS = smem_u32(dsm);          // A: 512 rows x 64B = 32KB
    unsigned bS[2] = { aS + 32768u, aS + 40960u };

    {
        const char* aG = (const char*)g_best4_u + (size_t)mhalf * 32768;
        #pragma unroll
        for (int rr = 0; rr < 2; rr++) {
            int row = tid + rr*256;
            #pragma unroll
            for (int j = 0; j < 4; j++)
                cp16(aS + sw64(row, j), aG + row*64 + j*16);
        }
    }
    load_tileB(bS[0], (const char*)g_emb4_u + (size_t)t0 * 8192, tid);
    CP_COMMIT();

    int rloc = (lane & 7) + ((lane >> 3) & 1) * 8;
    int kcA = lane >> 4;
    int rBl = ((lane >> 4) & 1) * 8 + (lane & 7);
    int khB = (lane >> 3) & 1;

    unsigned a[4][2][4];
    float acc[8];
    #pragma unroll
    for (int j = 0; j < 8; j++) acc[j] = 0.f;

    #pragma unroll 1
    for (int t = 0; t < cnt; t++) {
        if (t + 1 < cnt) {
            load_tileB(bS[(t + 1) & 1], (const char*)g_emb4_u + (size_t)(t0 + t + 1) * 8192, tid);
            CP_COMMIT();
            CP_WAIT(1);
        } else {
            CP_WAIT(0);
        }
        __syncthreads();

        if (t == 0) {
            #pragma unroll
            for (int f = 0; f < 4; f++) {
                int r = wid*64 + f*16 + rloc;
                #pragma unroll
                for (int k = 0; k < 2; k++) {
                    int c16 = k*2 + kcA;
                    ldsm_x4(a[f][k][0], a[f][k][1], a[f][k][2], a[f][k][3],
                            aS + sw64(r, c16));
                }
            }
        }

        unsigned bb = bS[t & 1];
        #pragma unroll 1
        for (int np = 0; np < 8; np++) {
            int rB = np*16 + rBl;
            float cc[32];
            #pragma unroll
            for (int j = 0; j < 32; j++) cc[j] = 0.f;
            #pragma unroll
            for (int k = 0; k < 2; k++) {
                int c16 = k*2 + khB;
                unsigned b0, b1, b2, b3;
                ldsm_x4(b0, b1, b2, b3, bb + sw64(rB, c16));
                #pragma unroll
                for (int f = 0; f < 4; f++) {
                    mma16816(cc + f*8,     a[f][k], b0, b1);
                    mma16816(cc + f*8 + 4, a[f][k], b2, b3);
                }
            }
            #pragma unroll
            for (int f = 0; f < 4; f++) {
                acc[f*2]   += ex2f(cc[f*8+0]) + ex2f(cc[f*8+1]) + ex2f(cc[f*8+4]) + ex2f(cc[f*8+5]);
                acc[f*2+1] += ex2f(cc[f*8+2]) + ex2f(cc[f*8+3]) + ex2f(cc[f*8+6]) + ex2f(cc[f*8+7]);
            }
        }
        __syncthreads();
    }

    #pragma unroll
    for (int j = 0; j < 8; j++) {
        acc[j] += __shfl_xor_sync(0xffffffffu, acc[j], 1);
        acc[j] += __shfl_xor_sync(0xffffffffu, acc[j], 2);
    }
    if ((lane & 3) == 0) {
        int r0 = mhalf*512 + wid*64 + (lane >> 2);
        #pragma unroll
        for (int f = 0; f < 4; f++) {
            g_partial[c*Bn + r0 + f*16]     = acc[f*2];
            g_partial[c*Bn + r0 + f*16 + 8] = acc[f*2+1];
        }
    }
}

// ---------------- final loss reduction ----------------
__global__ __launch_bounds__(1024) void k_e(float* __restrict__ loss_out) {
    __shared__ float red[1024];
    int tid = threadIdx.x;
    float acc = -96.0f;   // remove exp(0)=1 from the 96 zero-padded v columns
    for (int c = 0; c < NCHUNK; c++) acc += g_partial[c*Bn + tid];
    red[tid] = g_tgt[tid] - logf(acc);
    __syncthreads();
    for (int s = 512; s > 0; s >>= 1) { if (tid < s) red[tid] += red[tid+s]; __syncthreads(); }
    if (tid == 0) loss_out[0] = -red[0] / (float)Bn;
}

// ---------------- host launcher ----------------
extern "C" void kernel_launch(void* const* d_in, const int* in_sizes, int n_in,
                              void* d_out, int out_size) {
    const int*   item_seq = (const int*)  d_in[0];
    const float* mask     = (const float*)d_in[1];
    const int*   item     = (const int*)  d_in[2];
    const float* emb      = (const float*)d_in[3];
    const float* W        = (const float*)d_in[4];
    const float* cw0      = (const float*)d_in[5];
    float* out = (float*)d_out;

    float *ue_ptr, *loss_ptr;
    if (out_size >= BKH + 1)      { ue_ptr = out;          loss_ptr = out + BKH; }
    else if (out_size == BKH)     { ue_ptr = out;          loss_ptr = g_loss_scratch; }
    else                          { ue_ptr = g_ue_scratch; loss_ptr = out + (out_size > 0 ? out_size - 1 : 0); }

    cudaFuncSetAttribute(k_h_mma, cudaFuncAttributeMaxDynamicSharedMemorySize, KH_SMEM);
    cudaFuncSetAttribute(k_d_mma, cudaFuncAttributeMaxDynamicSharedMemorySize, KD_SMEM);

    cudaStream_t s2; cudaEvent_t evF, evR, evE;
    cudaStreamCreateWithFlags(&s2, cudaStreamNonBlocking);
    cudaEventCreateWithFlags(&evF, cudaEventDisableTiming);
    cudaEventCreateWithFlags(&evR, cudaEventDisableTiming);
    cudaEventCreateWithFlags(&evE, cudaEventDisableTiming);
    cudaEventRecord(evF, 0);
    cudaStreamWaitEvent(s2, evF, 0);

    // launch #1 (s2): colsum for iter 0 straight from cw0
    k_r1<true><<<KSn, 256, 0, s2>>>(cw0);
    cudaEventRecord(evR, s2);

    // launches #2, #3 (main): conv_w -> k_h
    k_conv_w<<<(Hn*64)/256, 256>>>(W);
    k_h_mma<<<(Bn*Sn)/128, 256, KH_SMEM>>>(item_seq, emb);

    cudaStreamWaitEvent(0, evR, 0);
    // launch #4 (main): first routing iteration  <-- ncu capture slot
    k_r2<0><<<Bn, 256>>>(mask, cw0, item, emb, ue_ptr);

    // launch #5 (s2): emb4 conversion (needed only by k_d)
    k_conv_emb4<<<(VP*16)/256, 256, 0, s2>>>(emb);
    cudaEventRecord(evE, s2);

    // remaining routing chain (main)
    k_r1<false><<<KSn, 256>>>(cw0);
    k_r2<1><<<Bn, 256>>>(mask, cw0, item, emb, ue_ptr);
    k_r1<false><<<KSn, 256>>>(cw0);
    k_r2<2><<<Bn, 256>>>(mask, cw0, item, emb, ue_ptr);

    cudaStreamWaitEvent(0, evE, 0);              // emb4 ready
    k_d_mma<<<dim3(NCHUNK, 2), 256, KD_SMEM>>>();
    k_e<<<1, 1024>>>(loss_ptr);
}